// round 16
// baseline (speedup 1.0000x reference)
#include <cuda_runtime.h>
#include <cstdint>

#define NTHR 256
#define S_ELEMS 2048                      // elements per tensor per stage
#define S_BYTES (S_ELEMS * 4)             // 8 KB per tensor per stage
#define VPT (S_ELEMS / 4 / NTHR)          // 2 float4 per thread per tensor per stage
#define PF_DIST 2                         // prefetch-ahead distance in stages
#define MAXBLK 2048

// Per-block partials, SoA: g_partials[c*MAXBLK + block], c in 0..11
// [0..3]=count(pred==c) [4..7]=count(label==c) [8..11]=count(pred==label==c)
__device__ unsigned int g_partials[12 * MAXBLK];
__device__ unsigned int g_ticket;   // zero-init at load; reset by last block each run

// Fire-and-forget DRAM->L2 prefetch (async engine, no completion, no smem)
#define PF_L2(ptr, bytes) \
    asm volatile("cp.async.bulk.prefetch.L2.global [%0], %1;" \
                 :: "l"(ptr), "r"(bytes) : "memory")

// count one vec4 pair into packed accumulators ap/al/ae
#define COUNT_PAIR(pv, lv) do {                                                  \
    int p0 = (int)(__float_as_uint((pv).x + 12582912.0f) & 3u);                  \
    int p1 = (int)(__float_as_uint((pv).y + 12582912.0f) & 3u);                  \
    int p2 = (int)(__float_as_uint((pv).z + 12582912.0f) & 3u);                  \
    int p3 = (int)(__float_as_uint((pv).w + 12582912.0f) & 3u);                  \
    ap += (1u << (p0 << 3)) + (1u << (p1 << 3))                                  \
        + (1u << (p2 << 3)) + (1u << (p3 << 3));                                 \
    al += (1u << ((lv).x << 3)) + (1u << ((lv).y << 3))                          \
        + (1u << ((lv).z << 3)) + (1u << ((lv).w << 3));                         \
    ae += (p0 == (lv).x ? (1u << (p0 << 3)) : 0u)                                \
        + (p1 == (lv).y ? (1u << (p1 << 3)) : 0u)                                \
        + (p2 == (lv).z ? (1u << (p2 << 3)) : 0u)                                \
        + (p3 == (lv).w ? (1u << (p3 << 3)) : 0u);                               \
} while (0)

__global__ __launch_bounds__(NTHR, 6) void iou_pf_kernel(
    const float* __restrict__ preds,
    const int*   __restrict__ labels,
    long long n,
    float* __restrict__ out)
{
    __shared__ unsigned int s[12];
    __shared__ bool s_last;

    const int tid = threadIdx.x;
    const unsigned int G = gridDim.x;
    const long long total_stages = n / S_ELEMS;

    if (tid < 12) s[tid] = 0u;

    // ---- Prologue: prefetch this CTA's first PF_DIST stages into L2 ----
    if (tid == 0) {
        #pragma unroll
        for (int d = 0; d < PF_DIST; d++) {
            long long st = (long long)blockIdx.x + (long long)d * G;
            if (st < total_stages) {
                PF_L2(preds  + st * S_ELEMS, (unsigned int)S_BYTES);
                PF_L2(labels + st * S_ELEMS, (unsigned int)S_BYTES);
            }
        }
    }

    unsigned int fp[4] = {0u,0u,0u,0u};
    unsigned int fl[4] = {0u,0u,0u,0u};
    unsigned int fe[4] = {0u,0u,0u,0u};
    unsigned int ap = 0u, al = 0u, ae = 0u;
    int pend = 0;

#define FLUSH_PACKED() do {                                   \
        _Pragma("unroll")                                     \
        for (int c = 0; c < 4; c++) {                         \
            fp[c] += (ap >> (8*c)) & 0xFFu;                   \
            fl[c] += (al >> (8*c)) & 0xFFu;                   \
            fe[c] += (ae >> (8*c)) & 0xFFu;                   \
        }                                                     \
        ap = 0u; al = 0u; ae = 0u; pend = 0;                  \
    } while (0)

    // ---- Mainloop: prefetch stage k+PF_DIST, consume stage k from L2 ----
    for (long long k = 0; ; k++) {
        long long st = (long long)blockIdx.x + k * G;
        if (st >= total_stages) break;

        if (tid == 0) {
            long long pst = st + (long long)PF_DIST * G;
            if (pst < total_stages) {
                PF_L2(preds  + pst * S_ELEMS, (unsigned int)S_BYTES);
                PF_L2(labels + pst * S_ELEMS, (unsigned int)S_BYTES);
            }
        }

        const float4* bp = (const float4*)(preds)  + st * (S_ELEMS / 4);
        const int4*   bl = (const int4*)  (labels) + st * (S_ELEMS / 4);

        // 4 front-batched LDG.128 (expected L2-hit), then count.
        float4 pv[VPT];
        int4   lv[VPT];
        #pragma unroll
        for (int v = 0; v < VPT; v++) pv[v] = __ldcg(&bp[v * NTHR + tid]);
        #pragma unroll
        for (int v = 0; v < VPT; v++) lv[v] = __ldcg(&bl[v * NTHR + tid]);
        #pragma unroll
        for (int v = 0; v < VPT; v++) COUNT_PAIR(pv[v], lv[v]);

        pend += VPT;
        if (pend >= 60) FLUSH_PACKED();   // 60 vec4 * 4 = 240 < 255: no overflow
    }
    FLUSH_PACKED();

    // ---- Scalar tail (elements beyond full stages) ----
    for (long long j = total_stages * S_ELEMS + (long long)blockIdx.x * NTHR + tid;
         j < n; j += (long long)G * NTHR) {
        int p = (int)preds[j];
        int l = labels[j];
        ap += 1u << (p << 3);
        al += 1u << (l << 3);
        ae += (p == l) ? (1u << (p << 3)) : 0u;
        if (++pend >= 60) FLUSH_PACKED();
    }
    FLUSH_PACKED();
#undef FLUSH_PACKED

    // ---- Warp reduction via REDUX ----
    #pragma unroll
    for (int c = 0; c < 4; c++) {
        fp[c] = __reduce_add_sync(0xFFFFFFFFu, fp[c]);
        fl[c] = __reduce_add_sync(0xFFFFFFFFu, fl[c]);
        fe[c] = __reduce_add_sync(0xFFFFFFFFu, fe[c]);
    }

    __syncthreads();
    if ((tid & 31) == 0) {
        #pragma unroll
        for (int c = 0; c < 4; c++) {
            atomicAdd(&s[c],     fp[c]);
            atomicAdd(&s[4 + c], fl[c]);
            atomicAdd(&s[8 + c], fe[c]);
        }
    }
    __syncthreads();

    if (tid < 12)
        g_partials[tid * MAXBLK + blockIdx.x] = s[tid];

    __threadfence();
    __syncthreads();

    if (tid == 0) {
        unsigned int old = atomicAdd(&g_ticket, 1u);
        s_last = (old == gridDim.x - 1u);
    }
    __syncthreads();

    if (s_last) {
        unsigned int loc[12];
        #pragma unroll
        for (int c = 0; c < 12; c++) loc[c] = 0u;

        for (unsigned int j = tid; j < gridDim.x; j += NTHR) {
            #pragma unroll
            for (int c = 0; c < 12; c++)
                loc[c] += __ldcg(&g_partials[c * MAXBLK + j]);
        }
        #pragma unroll
        for (int c = 0; c < 12; c++)
            loc[c] = __reduce_add_sync(0xFFFFFFFFu, loc[c]);

        __shared__ unsigned int s_tot[12];
        if (tid < 12) s_tot[tid] = 0u;
        __syncthreads();
        if ((tid & 31) == 0) {
            #pragma unroll
            for (int c = 0; c < 12; c++) atomicAdd(&s_tot[c], loc[c]);
        }
        __syncthreads();

        if (tid < 4) {
            int c = tid;
            float inter = (float)s_tot[8 + c];
            float uni   = (float)s_tot[c] + (float)s_tot[4 + c] - inter;
            float iou   = (uni == 0.0f) ? 1.0f : (inter / uni);
            out[c] = 1.0f - 100.0f * iou;
        }
        if (tid == 0)
            atomicExch(&g_ticket, 0u);   // reset for next graph replay
    }
}

extern "C" void kernel_launch(void* const* d_in, const int* in_sizes, int n_in,
                              void* d_out, int out_size)
{
    const float* preds  = (const float*)d_in[0];
    const int*   labels = (const int*)d_in[1];
    float*       out    = (float*)d_out;

    long long n = (long long)in_sizes[0];

    static int nsm = 0;
    if (nsm == 0) {
        int dev = 0;
        cudaGetDevice(&dev);
        cudaDeviceGetAttribute(&nsm, cudaDevAttrMultiProcessorCount, dev);
        if (nsm <= 0) nsm = 148;
    }
    int nblk = 6 * nsm;          // single wave at 6 CTAs/SM
    if (nblk > MAXBLK) nblk = MAXBLK;

    iou_pf_kernel<<<nblk, NTHR>>>(preds, labels, n, out);
}